// round 2
// baseline (speedup 1.0000x reference)
#include <cuda_runtime.h>

typedef unsigned long long ull;

#define HDIM 64
#define MAXT 256
#define MAXB 16384
#define NTHR 192

// ---------------- device globals (no allocation allowed) ----------------
__device__ int g_tok64;
__device__ int g_pos64;
__device__ int g_hist[256];
__device__ int g_cursor[256];
__device__ int g_order[MAXB];

// ---------------- helpers ----------------
__device__ __forceinline__ ull ffma2(ull a, ull b, ull c) {
  ull d;
  asm("fma.rn.f32x2 %0, %1, %2, %3;" : "=l"(d) : "l"(a), "l"(b), "l"(c));
  return d;
}
__device__ __forceinline__ float pair_sum(ull a) {
  unsigned lo, hi;
  asm("mov.b64 {%0, %1}, %2;" : "=r"(lo), "=r"(hi) : "l"(a));
  return __uint_as_float(lo) + __uint_as_float(hi);
}
__device__ __forceinline__ float sigm(float x) {
  // 1/(1+e^-x); saturates correctly at +/-inf via rcp
  return __frcp_rn(1.0f + __expf(-x));
}
__device__ __forceinline__ float tanh_f(float x) {
  // 1 - 2/(e^{2x}+1); exact limits at +/-1, ~1e-6 rel error
  return 1.0f - 2.0f * __frcp_rn(__expf(2.0f * x) + 1.0f);
}

__device__ __forceinline__ int load_len_(const void* sp, int b, int T, int p64) {
  int v = p64 ? (int)((const long long*)sp)[b] : ((const int*)sp)[b];
  return min(max(v, 1), T);
}
__device__ __forceinline__ int load_tok_(const void* st, long long idx, int t64) {
  return t64 ? (int)((const long long*)st)[idx] : ((const int*)st)[idx];
}

// ---------------- dtype detection (int64 vs int32) ----------------
// seq_pos values are in [1,200]; if stored int64, every odd 32-bit word is 0.
// If stored int32, odd words are values >= 1 -> perfect discriminator.
// seq_token values in [0,1e5): check 16 odd words (P[false int64] ~ 1e-80).
__global__ void k_detect(const int* tok, const int* pos) {
  if (threadIdx.x == 0) {
    int t64 = 1, p64 = 1;
#pragma unroll
    for (int i = 1; i < 32; i += 2) {
      if (tok[i] != 0) t64 = 0;
      if (pos[i] != 0) p64 = 0;
    }
    g_tok64 = t64;
    g_pos64 = p64;
  }
}

// ---------------- counting sort by length (descending) ----------------
__global__ void k_zero() { g_hist[threadIdx.x] = 0; }

__global__ void k_hist(const void* pos, int B, int T) {
  int b = blockIdx.x * blockDim.x + threadIdx.x;
  if (b < B) {
    int len = load_len_(pos, b, T, g_pos64);
    int bin = min(T - len, 255);  // bin 0 = longest
    atomicAdd(&g_hist[bin], 1);
  }
}

__global__ void k_scan() {
  __shared__ int v[256];
  int i = threadIdx.x;
  int x = g_hist[i];
  v[i] = x;
  __syncthreads();
#pragma unroll
  for (int off = 1; off < 256; off <<= 1) {
    int t = (i >= off) ? v[i - off] : 0;
    __syncthreads();
    v[i] += t;
    __syncthreads();
  }
  g_cursor[i] = v[i] - x;  // exclusive prefix
}

__global__ void k_scatter(const void* pos, int B, int T) {
  int b = blockIdx.x * blockDim.x + threadIdx.x;
  if (b < B) {
    int len = load_len_(pos, b, T, g_pos64);
    int bin = min(T - len, 255);
    int p = atomicAdd(&g_cursor[bin], 1);
    if (p < MAXB) g_order[p] = b;
  }
}

// ---------------- fused GRU recurrence ----------------
// CTA = 192 threads = (gate g in 0..2) x (unit j in 0..63), each thread owns
// TWO batch rows (shared W registers). W rows live in registers (128 regs).
// x/h broadcast from smem (LDS.128, N=1). 2 barriers per timestep.
__global__ void __launch_bounds__(NTHR, 2) k_gru(
    const void* __restrict__ seq_token, const void* __restrict__ seq_pos,
    const float* __restrict__ emb, const float* __restrict__ W_ih,
    const float* __restrict__ W_hh, float* __restrict__ out, int B, int T) {
  __shared__ int tok_sm[2][MAXT];
  __shared__ __align__(16) float x_sm[2][2][HDIM];  // [buf][row][j]
  __shared__ __align__(16) float h_sm[2][HDIM];
  __shared__ float r_sm[2][HDIM];
  __shared__ float z_sm[2][HDIM];
  __shared__ int s_row[2], s_len[2];

  const int tid = threadIdx.x;
  const int g = tid >> 6;  // gate (warp-uniform)
  const int j = tid & 63;
  const int tok64 = g_tok64;

  if (tid < 2) {
    int idx = 2 * blockIdx.x + tid;
    int row = (idx < B) ? g_order[idx] : -1;
    s_row[tid] = row;
    s_len[tid] = (row >= 0) ? load_len_(seq_pos, row, T, g_pos64) : 0;
  }
  __syncthreads();
  const int row0 = s_row[0], row1 = s_row[1];
  const int len0 = s_len[0], len1 = s_len[1];
  int tmax = max(len0, len1);
  if (tmax > MAXT) tmax = MAXT;  // safety (T=200 in practice)

  // stage token ids (int32) into smem
  {
    int rA = row0;
    for (int i = tid; i < tmax; i += NTHR)
      tok_sm[0][i] = (rA >= 0) ? load_tok_(seq_token, (long long)rA * T + i, tok64) : 0;
    int rB = row1;
    for (int i = tid; i < tmax; i += NTHR)
      tok_sm[1][i] = (rB >= 0) ? load_tok_(seq_token, (long long)rB * T + i, tok64) : 0;
  }

  // weights for this (gate, j) output unit: 64+64 floats -> 128 registers
  ull wih[32], whh[32];
  {
    const ulonglong2* wi = (const ulonglong2*)(W_ih + (g * 64 + j) * HDIM);
    const ulonglong2* wh = (const ulonglong2*)(W_hh + (g * 64 + j) * HDIM);
#pragma unroll
    for (int k = 0; k < 16; k++) {
      ulonglong2 a = wi[k];
      wih[2 * k] = a.x;
      wih[2 * k + 1] = a.y;
      ulonglong2 b = wh[k];
      whh[2 * k] = b.x;
      whh[2 * k + 1] = b.y;
    }
  }
  __syncthreads();  // tok_sm ready

  // init h = 0, load x for t=0
  if (tid < 128) {
    int r = tid >> 6, jj = tid & 63;
    h_sm[r][jj] = 0.0f;
    x_sm[0][r][jj] = emb[(long long)tok_sm[r][0] * HDIM + jj];
  }
  __syncthreads();

  for (int t = 0; t < tmax; t++) {
    const int cur = t & 1, nxt = cur ^ 1;

    // prefetch next-step embedding rows (hidden under this step's compute)
    float xn0 = 0.0f, xn1 = 0.0f;
    const bool pf = (g == 0) && (t + 1 < tmax);
    if (pf) {
      xn0 = emb[(long long)tok_sm[0][t + 1] * HDIM + j];
      xn1 = emb[(long long)tok_sm[1][t + 1] * HDIM + j];
    }

    const ulonglong2* xv0 = (const ulonglong2*)x_sm[cur][0];
    const ulonglong2* xv1 = (const ulonglong2*)x_sm[cur][1];
    const ulonglong2* hv0 = (const ulonglong2*)h_sm[0];
    const ulonglong2* hv1 = (const ulonglong2*)h_sm[1];

    // row 0 dot products (packed f32x2 FMA)
    ull ai0 = 0ull, ah0 = 0ull;
#pragma unroll
    for (int k = 0; k < 16; k++) {
      ulonglong2 xq = xv0[k];
      ulonglong2 hq = hv0[k];
      ai0 = ffma2(wih[2 * k], xq.x, ai0);
      ai0 = ffma2(wih[2 * k + 1], xq.y, ai0);
      ah0 = ffma2(whh[2 * k], hq.x, ah0);
      ah0 = ffma2(whh[2 * k + 1], hq.y, ah0);
    }
    // row 1
    ull ai1 = 0ull, ah1 = 0ull;
#pragma unroll
    for (int k = 0; k < 16; k++) {
      ulonglong2 xq = xv1[k];
      ulonglong2 hq = hv1[k];
      ai1 = ffma2(wih[2 * k], xq.x, ai1);
      ai1 = ffma2(wih[2 * k + 1], xq.y, ai1);
      ah1 = ffma2(whh[2 * k], hq.x, ah1);
      ah1 = ffma2(whh[2 * k + 1], hq.y, ah1);
    }

    const float pi0 = pair_sum(ai0), ph0 = pair_sum(ah0);
    const float pi1 = pair_sum(ai1), ph1 = pair_sum(ah1);

    if (g == 0) {
      r_sm[0][j] = sigm(pi0 + ph0);
      r_sm[1][j] = sigm(pi1 + ph1);
    } else if (g == 1) {
      z_sm[0][j] = sigm(pi0 + ph0);
      z_sm[1][j] = sigm(pi1 + ph1);
    }
    __syncthreads();  // r,z published; all x/h reads of this step done

    if (g == 2) {
      {
        float r = r_sm[0][j], z = z_sm[0][j];
        float n = tanh_f(pi0 + r * ph0);
        float ho = h_sm[0][j];
        if (t < len0) h_sm[0][j] = (1.0f - z) * n + z * ho;
      }
      {
        float r = r_sm[1][j], z = z_sm[1][j];
        float n = tanh_f(pi1 + r * ph1);
        float ho = h_sm[1][j];
        if (t < len1) h_sm[1][j] = (1.0f - z) * n + z * ho;
      }
    }
    if (pf) {
      x_sm[nxt][0][j] = xn0;
      x_sm[nxt][1][j] = xn1;
    }
    __syncthreads();  // h updated, next x staged
  }

  __syncthreads();
  if (tid < 128) {
    int r = tid >> 6, jj = tid & 63;
    int row = (r == 0) ? row0 : row1;
    if (row >= 0) out[(long long)row * HDIM + jj] = h_sm[r][jj];
  }
}

// ---------------- launch ----------------
extern "C" void kernel_launch(void* const* d_in, const int* in_sizes, int n_in,
                              void* d_out, int out_size) {
  const void* tok = d_in[0];
  const void* pos = d_in[1];
  const float* emb = (const float*)d_in[2];
  const float* wih = (const float*)d_in[3];
  const float* whh = (const float*)d_in[4];
  float* out = (float*)d_out;

  const int B = in_sizes[1];                 // seq_pos element count
  const int T = in_sizes[0] / (B > 0 ? B : 1);

  k_detect<<<1, 32>>>((const int*)tok, (const int*)pos);
  k_zero<<<1, 256>>>();
  k_hist<<<(B + 255) / 256, 256>>>(pos, B, T);
  k_scan<<<1, 256>>>();
  k_scatter<<<(B + 255) / 256, 256>>>(pos, B, T);

  const int nblk = (B + 1) / 2;  // 2 rows per CTA
  k_gru<<<nblk, NTHR>>>(tok, pos, emb, wih, whh, out, B, T);
}

// round 3
// speedup vs baseline: 1.1651x; 1.1651x over previous
#include <cuda_runtime.h>

typedef unsigned long long ull;

#define HDIM 64
#define MAXT 256
#define MAXB 16384
#define NTHR 192
#define ROWS 4

// ---------------- device globals (no allocation allowed) ----------------
__device__ int g_tok64;
__device__ int g_pos64;
__device__ int g_hist[256];
__device__ int g_order[MAXB];

// ---------------- helpers ----------------
__device__ __forceinline__ ull ffma2(ull a, ull b, ull c) {
  ull d;
  asm("fma.rn.f32x2 %0, %1, %2, %3;" : "=l"(d) : "l"(a), "l"(b), "l"(c));
  return d;
}
__device__ __forceinline__ float pair_sum(ull a) {
  unsigned lo, hi;
  asm("mov.b64 {%0, %1}, %2;" : "=r"(lo), "=r"(hi) : "l"(a));
  return __uint_as_float(lo) + __uint_as_float(hi);
}
__device__ __forceinline__ float rcp_fast(float x) {
  float y;
  asm("rcp.approx.f32 %0, %1;" : "=f"(y) : "f"(x));
  return y;
}
__device__ __forceinline__ float sigm(float x) {
  // 1/(1+e^-x); exp->inf gives rcp(inf)=0, correct saturation
  return rcp_fast(1.0f + __expf(-x));
}
__device__ __forceinline__ float tanh_f(float x) {
  // 1 - 2/(e^{2x}+1); exact limits at +/-1
  return 1.0f - 2.0f * rcp_fast(__expf(2.0f * x) + 1.0f);
}

__device__ __forceinline__ int load_len_(const void* sp, int b, int T, int p64) {
  int v = p64 ? (int)((const long long*)sp)[b] : ((const int*)sp)[b];
  return min(max(v, 1), T);
}
__device__ __forceinline__ int load_tok_(const void* st, long long idx, int t64) {
  return t64 ? (int)((const long long*)st)[idx] : ((const int*)st)[idx];
}

// dot products for a pair of rows (packed f32x2 FMA, W in registers)
__device__ __forceinline__ void dot2(const ull* __restrict__ wih,
                                     const ull* __restrict__ whh,
                                     const float* xA, const float* hA,
                                     const float* xB, const float* hB,
                                     float& piA, float& phA, float& piB,
                                     float& phB) {
  const ulonglong2* xvA = (const ulonglong2*)xA;
  const ulonglong2* hvA = (const ulonglong2*)hA;
  const ulonglong2* xvB = (const ulonglong2*)xB;
  const ulonglong2* hvB = (const ulonglong2*)hB;
  ull aiA = 0ull, ahA = 0ull, aiB = 0ull, ahB = 0ull;
#pragma unroll
  for (int k = 0; k < 16; k++) {
    ulonglong2 xqA = xvA[k];
    ulonglong2 hqA = hvA[k];
    aiA = ffma2(wih[2 * k], xqA.x, aiA);
    aiA = ffma2(wih[2 * k + 1], xqA.y, aiA);
    ahA = ffma2(whh[2 * k], hqA.x, ahA);
    ahA = ffma2(whh[2 * k + 1], hqA.y, ahA);
    ulonglong2 xqB = xvB[k];
    ulonglong2 hqB = hvB[k];
    aiB = ffma2(wih[2 * k], xqB.x, aiB);
    aiB = ffma2(wih[2 * k + 1], xqB.y, aiB);
    ahB = ffma2(whh[2 * k], hqB.x, ahB);
    ahB = ffma2(whh[2 * k + 1], hqB.y, ahB);
  }
  piA = pair_sum(aiA);
  phA = pair_sum(ahA);
  piB = pair_sum(aiB);
  phB = pair_sum(ahB);
}

// ---------------- preamble kernels (3 launches -> k_gru lands at ncu idx 5) --
// dtype detection: seq_pos values >=1, seq_token < 1e5; if int64, odd 32-bit
// words are all zero. Also zero the histogram.
__global__ void k_prep(const int* tok, const int* pos) {
  if (threadIdx.x == 0) {
    int t64 = 1, p64 = 1;
#pragma unroll
    for (int i = 1; i < 32; i += 2) {
      if (tok[i] != 0) t64 = 0;
      if (pos[i] != 0) p64 = 0;
    }
    g_tok64 = t64;
    g_pos64 = p64;
  }
  g_hist[threadIdx.x] = 0;
}

__global__ void k_hist(const void* pos, int B, int T) {
  int b = blockIdx.x * blockDim.x + threadIdx.x;
  if (b < B) {
    int len = load_len_(pos, b, T, g_pos64);
    int bin = min(T - len, 255);  // bin 0 = longest
    atomicAdd(&g_hist[bin], 1);
  }
}

// single-CTA: exclusive scan of hist, then scatter all B rows (sorted by
// descending length -> g_order)
__global__ void k_scanscatter(const void* pos, int B, int T) {
  __shared__ int v[256];
  __shared__ int cur[256];
  int i = threadIdx.x;
  int x = g_hist[i];
  v[i] = x;
  __syncthreads();
#pragma unroll
  for (int off = 1; off < 256; off <<= 1) {
    int t = (i >= off) ? v[i - off] : 0;
    __syncthreads();
    v[i] += t;
    __syncthreads();
  }
  cur[i] = v[i] - x;  // exclusive prefix
  __syncthreads();
  int p64 = g_pos64;
  for (int b = i; b < B; b += 256) {
    int len = load_len_(pos, b, T, p64);
    int bin = min(T - len, 255);
    int p = atomicAdd(&cur[bin], 1);
    if (p < MAXB) g_order[p] = b;
  }
}

// ---------------- fused GRU recurrence ----------------
// CTA = 192 threads = (gate g in 0..2) x (unit j in 0..63); each CTA owns FOUR
// batch rows (adjacent in length-sorted order). W rows live in registers
// (128 regs, shared across the 4 rows). x/h broadcast from smem (LDS.128,
// conflict-free). 2 barriers per timestep.
__global__ void __launch_bounds__(NTHR, 2) k_gru(
    const void* __restrict__ seq_token, const void* __restrict__ seq_pos,
    const float* __restrict__ emb, const float* __restrict__ W_ih,
    const float* __restrict__ W_hh, float* __restrict__ out, int B, int T) {
  __shared__ int tok_sm[ROWS][MAXT];
  __shared__ __align__(16) float x_sm[2][ROWS][HDIM];  // [buf][row][j]
  __shared__ __align__(16) float h_sm[ROWS][HDIM];
  __shared__ float r_sm[ROWS][HDIM];
  __shared__ float z_sm[ROWS][HDIM];
  __shared__ int s_row[ROWS], s_len[ROWS];

  const int tid = threadIdx.x;
  const int g = tid >> 6;  // gate (warp-uniform)
  const int j = tid & 63;
  const int tok64 = g_tok64;

  if (tid < ROWS) {
    int idx = ROWS * blockIdx.x + tid;
    int row = (idx < B) ? g_order[idx] : -1;
    s_row[tid] = row;
    s_len[tid] = (row >= 0) ? load_len_(seq_pos, row, T, g_pos64) : 0;
  }
  __syncthreads();
  int rows[ROWS], lens[ROWS];
  int tmax = 0;
#pragma unroll
  for (int r = 0; r < ROWS; r++) {
    rows[r] = s_row[r];
    lens[r] = s_len[r];
    tmax = max(tmax, lens[r]);
  }
  if (tmax > MAXT) tmax = MAXT;

  // stage token ids (as int32) into smem
#pragma unroll
  for (int r = 0; r < ROWS; r++) {
    int rw = rows[r];
    for (int i = tid; i < tmax; i += NTHR)
      tok_sm[r][i] = (rw >= 0) ? load_tok_(seq_token, (long long)rw * T + i, tok64) : 0;
  }

  // weights for this (gate, j) output unit: 64+64 floats -> 128 registers
  ull wih[32], whh[32];
  {
    const ulonglong2* wi = (const ulonglong2*)(W_ih + (g * 64 + j) * HDIM);
    const ulonglong2* wh = (const ulonglong2*)(W_hh + (g * 64 + j) * HDIM);
#pragma unroll
    for (int k = 0; k < 16; k++) {
      ulonglong2 a = wi[k];
      wih[2 * k] = a.x;
      wih[2 * k + 1] = a.y;
      ulonglong2 b = wh[k];
      whh[2 * k] = b.x;
      whh[2 * k + 1] = b.y;
    }
  }
  __syncthreads();  // tok_sm ready

  // init h = 0, load x for t=0
  for (int idx = tid; idx < ROWS * HDIM; idx += NTHR) {
    int r = idx >> 6, jj = idx & 63;
    h_sm[r][jj] = 0.0f;
    x_sm[0][r][jj] = emb[(long long)tok_sm[r][0] * HDIM + jj];
  }
  __syncthreads();

  for (int t = 0; t < tmax; t++) {
    const int cur = t & 1, nxt = cur ^ 1;

    // prefetch next-step embedding rows (g0/g1 threads: 2 rows each)
    float xnA = 0.0f, xnB = 0.0f;
    const int pr = tid >> 6;  // 0 or 1 for prefetch threads
    const bool pf = (tid < 128) && (t + 1 < tmax);
    if (pf) {
      xnA = emb[(long long)tok_sm[pr][t + 1] * HDIM + j];
      xnB = emb[(long long)tok_sm[pr + 2][t + 1] * HDIM + j];
    }

    float pi0, ph0, pi1, ph1, pi2, ph2, pi3, ph3;
    dot2(wih, whh, x_sm[cur][0], h_sm[0], x_sm[cur][1], h_sm[1],
         pi0, ph0, pi1, ph1);
    dot2(wih, whh, x_sm[cur][2], h_sm[2], x_sm[cur][3], h_sm[3],
         pi2, ph2, pi3, ph3);

    if (g == 0) {
      r_sm[0][j] = sigm(pi0 + ph0);
      r_sm[1][j] = sigm(pi1 + ph1);
      r_sm[2][j] = sigm(pi2 + ph2);
      r_sm[3][j] = sigm(pi3 + ph3);
    } else if (g == 1) {
      z_sm[0][j] = sigm(pi0 + ph0);
      z_sm[1][j] = sigm(pi1 + ph1);
      z_sm[2][j] = sigm(pi2 + ph2);
      z_sm[3][j] = sigm(pi3 + ph3);
    }
    __syncthreads();  // r,z published; all x/h reads of this step done

    if (g == 2) {
      float pis[ROWS] = {pi0, pi1, pi2, pi3};
      float phs[ROWS] = {ph0, ph1, ph2, ph3};
#pragma unroll
      for (int r = 0; r < ROWS; r++) {
        float rr = r_sm[r][j], zz = z_sm[r][j];
        float n = tanh_f(pis[r] + rr * phs[r]);
        float ho = h_sm[r][j];
        if (t < lens[r]) h_sm[r][j] = (1.0f - zz) * n + zz * ho;
      }
    }
    if (pf) {
      x_sm[nxt][pr][j] = xnA;
      x_sm[nxt][pr + 2][j] = xnB;
    }
    __syncthreads();  // h updated, next x staged
  }

  __syncthreads();
  for (int idx = tid; idx < ROWS * HDIM; idx += NTHR) {
    int r = idx >> 6, jj = idx & 63;
    int row = rows[r];
    if (row >= 0) out[(long long)row * HDIM + jj] = h_sm[r][jj];
  }
}

// ---------------- launch ----------------
extern "C" void kernel_launch(void* const* d_in, const int* in_sizes, int n_in,
                              void* d_out, int out_size) {
  const void* tok = d_in[0];
  const void* pos = d_in[1];
  const float* emb = (const float*)d_in[2];
  const float* wih = (const float*)d_in[3];
  const float* whh = (const float*)d_in[4];
  float* out = (float*)d_out;

  const int B = in_sizes[1];  // seq_pos element count
  const int T = in_sizes[0] / (B > 0 ? B : 1);

  k_prep<<<1, 256>>>((const int*)tok, (const int*)pos);
  k_hist<<<(B + 255) / 256, 256>>>(pos, B, T);
  k_scanscatter<<<1, 256>>>(pos, B, T);

  const int nblk = (B + ROWS - 1) / ROWS;
  k_gru<<<nblk, NTHR>>>(tok, pos, emb, wih, whh, out, B, T);
}

// round 4
// speedup vs baseline: 1.4931x; 1.2815x over previous
#include <cuda_runtime.h>

typedef unsigned long long ull;
typedef long long ll;

#define HDIM 64
#define GDIM 192  // 3*HDIM
#define MAXT 256
#define MAXB 16384
#define MAXV 102400
#define NTHR 192
#define ROWS 8

// ---------------- device globals (no allocation allowed) ----------------
__device__ int g_tok64;
__device__ int g_pos64;
__device__ int g_hist[256];
__device__ int g_order[MAXB];
__device__ float g_proj[(size_t)MAXV * GDIM];  // emb @ W_ih^T, ~78.6MB

// ---------------- helpers ----------------
__device__ __forceinline__ ull ffma2(ull a, ull b, ull c) {
  ull d;
  asm("fma.rn.f32x2 %0, %1, %2, %3;" : "=l"(d) : "l"(a), "l"(b), "l"(c));
  return d;
}
__device__ __forceinline__ float pair_sum(ull a) {
  unsigned lo, hi;
  asm("mov.b64 {%0, %1}, %2;" : "=r"(lo), "=r"(hi) : "l"(a));
  return __uint_as_float(lo) + __uint_as_float(hi);
}
__device__ __forceinline__ float rcp_fast(float x) {
  float y;
  asm("rcp.approx.f32 %0, %1;" : "=f"(y) : "f"(x));
  return y;
}
__device__ __forceinline__ float sigm(float x) {
  return rcp_fast(1.0f + __expf(-x));
}
__device__ __forceinline__ float tanh_f(float x) {
  return 1.0f - 2.0f * rcp_fast(__expf(2.0f * x) + 1.0f);
}
__device__ __forceinline__ int load_len_(const void* sp, int b, int T, int p64) {
  int v = p64 ? (int)((const ll*)sp)[b] : ((const int*)sp)[b];
  return min(max(v, 1), T);
}
__device__ __forceinline__ int load_tok_(const void* st, ll idx, int t64) {
  return t64 ? (int)((const ll*)st)[idx] : ((const int*)st)[idx];
}

// ---------------- preamble 1: dtype detect + length histogram (1 CTA) -------
__global__ void k_prep(const int* tok, const int* pos, int B, int T) {
  __shared__ int h_sm[256];
  int i = threadIdx.x;
  if (i == 0) {
    int t64 = 1, p64 = 1;
#pragma unroll
    for (int k = 1; k < 32; k += 2) {
      if (tok[k] != 0) t64 = 0;
      if (pos[k] != 0) p64 = 0;
    }
    g_tok64 = t64;
    g_pos64 = p64;
  }
  h_sm[i] = 0;
  __syncthreads();
  int p64 = g_pos64;
  for (int b = i; b < B; b += 256) {
    int v = p64 ? (int)((const ll*)pos)[b] : pos[b];
    int len = min(max(v, 1), T);
    atomicAdd(&h_sm[min(T - len, 255)], 1);  // bin 0 = longest
  }
  __syncthreads();
  g_hist[i] = h_sm[i];
}

// ---------------- preamble 2: scan + scatter (1 CTA) ----------------
__global__ void k_scanscatter(const void* pos, int B, int T) {
  __shared__ int v[256];
  __shared__ int cur[256];
  int i = threadIdx.x;
  int x = g_hist[i];
  v[i] = x;
  __syncthreads();
#pragma unroll
  for (int off = 1; off < 256; off <<= 1) {
    int t = (i >= off) ? v[i - off] : 0;
    __syncthreads();
    v[i] += t;
    __syncthreads();
  }
  cur[i] = v[i] - x;
  __syncthreads();
  int p64 = g_pos64;
  for (int b = i; b < B; b += 256) {
    int len = load_len_(pos, b, T, p64);
    int bin = min(T - len, 255);
    int p = atomicAdd(&cur[bin], 1);
    if (p < MAXB) g_order[p] = b;
  }
}

// ---------------- vocab projection: g_proj = emb @ W_ih^T ----------------
// thread j owns W_ih row j in registers; CTA processes a contiguous vocab
// chunk, two rows per iteration, double-buffered emb staging.
__global__ void __launch_bounds__(GDIM, 3) k_proj(const float* __restrict__ emb,
                                                  const float* __restrict__ W_ih,
                                                  int V) {
  __shared__ __align__(16) float e_sm[2][2][HDIM];
  const int j = threadIdx.x;

  ull w[32];
  {
    const ulonglong2* wr = (const ulonglong2*)(W_ih + j * HDIM);
#pragma unroll
    for (int k = 0; k < 16; k++) {
      ulonglong2 a = wr[k];
      w[2 * k] = a.x;
      w[2 * k + 1] = a.y;
    }
  }

  int per = (V + gridDim.x - 1) / gridDim.x;
  per = (per + 1) & ~1;  // even
  const int vbeg = blockIdx.x * per;
  const int vend = min(vbeg + per, V);
  if (vbeg >= vend) return;

  // stage first pair into buf 0
  if (j < 32) {
    int row = j >> 4, lane = j & 15;
    int v = vbeg + row;
    if (v < vend)
      ((float4*)e_sm[0][row])[lane] = ((const float4*)(emb + (ll)v * HDIM))[lane];
  }
  __syncthreads();

  int buf = 0;
  for (int v = vbeg; v < vend; v += 2) {
    // stage next pair
    if (j < 32) {
      int row = j >> 4, lane = j & 15;
      int vn = v + 2 + row;
      if (vn < vend)
        ((float4*)e_sm[buf ^ 1][row])[lane] =
            ((const float4*)(emb + (ll)vn * HDIM))[lane];
    }
    // compute both rows of current pair
    ull acc0 = 0ull, acc1 = 0ull;
    const ulonglong2* e0 = (const ulonglong2*)e_sm[buf][0];
    const ulonglong2* e1 = (const ulonglong2*)e_sm[buf][1];
#pragma unroll
    for (int k = 0; k < 16; k++) {
      ulonglong2 q0 = e0[k];
      ulonglong2 q1 = e1[k];
      acc0 = ffma2(w[2 * k], q0.x, acc0);
      acc0 = ffma2(w[2 * k + 1], q0.y, acc0);
      acc1 = ffma2(w[2 * k], q1.x, acc1);
      acc1 = ffma2(w[2 * k + 1], q1.y, acc1);
    }
    g_proj[(ll)v * GDIM + j] = pair_sum(acc0);
    if (v + 1 < vend) g_proj[(ll)(v + 1) * GDIM + j] = pair_sum(acc1);
    __syncthreads();
    buf ^= 1;
  }
}

// ---------------- fused GRU recurrence ----------------
// CTA = 192 threads = (gate g in 0..2) x (unit j in 0..63); 8 rows per CTA
// (adjacent in length-sorted order). W_hh row in 64 registers. gi comes from
// g_proj gather (prefetched 1 step ahead). h broadcast from smem.
__global__ void __launch_bounds__(NTHR, 2) k_gru(
    const void* __restrict__ seq_token, const void* __restrict__ seq_pos,
    const float* __restrict__ W_hh, float* __restrict__ out, int B, int T) {
  __shared__ int tok_sm[ROWS][MAXT];
  __shared__ __align__(16) float h_sm[ROWS][HDIM];
  __shared__ float r_sm[ROWS][HDIM];
  __shared__ float z_sm[ROWS][HDIM];
  __shared__ int s_row[ROWS], s_len[ROWS];

  const int tid = threadIdx.x;
  const int g = tid >> 6;  // gate (warp-uniform)
  const int j = tid & 63;
  const int gj = g * HDIM + j;
  const int tok64 = g_tok64;

  if (tid < ROWS) {
    int idx = ROWS * blockIdx.x + tid;
    int row = (idx < B) ? g_order[idx] : -1;
    s_row[tid] = row;
    s_len[tid] = (row >= 0) ? load_len_(seq_pos, row, T, g_pos64) : 0;
  }
  __syncthreads();
  int rows[ROWS], lens[ROWS];
  int tmax = 0;
#pragma unroll
  for (int r = 0; r < ROWS; r++) {
    rows[r] = s_row[r];
    lens[r] = s_len[r];
    tmax = max(tmax, lens[r]);
  }
  if (tmax > MAXT) tmax = MAXT;

  // stage token ids (as int32) into smem
#pragma unroll
  for (int r = 0; r < ROWS; r++) {
    int rw = rows[r];
    for (int i = tid; i < tmax; i += NTHR)
      tok_sm[r][i] = (rw >= 0) ? load_tok_(seq_token, (ll)rw * T + i, tok64) : 0;
  }

  // W_hh row for this (gate, unit): 64 floats -> 64 registers
  ull whh[32];
  {
    const ulonglong2* wh = (const ulonglong2*)(W_hh + gj * HDIM);
#pragma unroll
    for (int k = 0; k < 16; k++) {
      ulonglong2 b = wh[k];
      whh[2 * k] = b.x;
      whh[2 * k + 1] = b.y;
    }
  }

  // init h = 0
  for (int idx = tid; idx < ROWS * HDIM; idx += NTHR) {
    int r = idx >> 6, jj = idx & 63;
    h_sm[r][jj] = 0.0f;
  }
  __syncthreads();  // tok_sm + h ready

  // gi for t=0
  float gi_cur[ROWS];
#pragma unroll
  for (int r = 0; r < ROWS; r++)
    gi_cur[r] = g_proj[(ll)tok_sm[r][0] * GDIM + gj];

  for (int t = 0; t < tmax; t++) {
    // prefetch gi for t+1 (hidden under this step's compute)
    float gi_nxt[ROWS];
    if (t + 1 < tmax) {
#pragma unroll
      for (int r = 0; r < ROWS; r++)
        gi_nxt[r] = g_proj[(ll)tok_sm[r][t + 1] * GDIM + gj];
    }

    // gh dot products: 8 independent f32x2 chains
    ull acc[ROWS];
#pragma unroll
    for (int r = 0; r < ROWS; r++) acc[r] = 0ull;
#pragma unroll
    for (int k = 0; k < 16; k++) {
#pragma unroll
      for (int r = 0; r < ROWS; r++) {
        ulonglong2 hq = ((const ulonglong2*)h_sm[r])[k];
        acc[r] = ffma2(whh[2 * k], hq.x, acc[r]);
        acc[r] = ffma2(whh[2 * k + 1], hq.y, acc[r]);
      }
    }
    float ph[ROWS];
#pragma unroll
    for (int r = 0; r < ROWS; r++) ph[r] = pair_sum(acc[r]);

    if (g == 0) {
#pragma unroll
      for (int r = 0; r < ROWS; r++) r_sm[r][j] = sigm(gi_cur[r] + ph[r]);
    } else if (g == 1) {
#pragma unroll
      for (int r = 0; r < ROWS; r++) z_sm[r][j] = sigm(gi_cur[r] + ph[r]);
    }
    __syncthreads();  // r,z published; all h reads of this step done

    if (g == 2) {
#pragma unroll
      for (int r = 0; r < ROWS; r++) {
        float rr = r_sm[r][j], zz = z_sm[r][j];
        float n = tanh_f(gi_cur[r] + rr * ph[r]);
        float ho = h_sm[r][j];
        if (t < lens[r]) h_sm[r][j] = (1.0f - zz) * n + zz * ho;
      }
    }
    __syncthreads();  // h updated

#pragma unroll
    for (int r = 0; r < ROWS; r++) gi_cur[r] = gi_nxt[r];
  }

  for (int idx = tid; idx < ROWS * HDIM; idx += NTHR) {
    int r = idx >> 6, jj = idx & 63;
    int row = rows[r];
    if (row >= 0) out[(ll)row * HDIM + jj] = h_sm[r][jj];
  }
}

// ---------------- launch ----------------
extern "C" void kernel_launch(void* const* d_in, const int* in_sizes, int n_in,
                              void* d_out, int out_size) {
  const void* tok = d_in[0];
  const void* pos = d_in[1];
  const float* emb = (const float*)d_in[2];
  const float* wih = (const float*)d_in[3];
  const float* whh = (const float*)d_in[4];
  float* out = (float*)d_out;

  const int B = in_sizes[1];
  const int T = in_sizes[0] / (B > 0 ? B : 1);
  int V = in_sizes[2] / HDIM;
  if (V > MAXV) V = MAXV;

  k_prep<<<1, 256>>>((const int*)tok, (const int*)pos, B, T);
  k_scanscatter<<<1, 256>>>(pos, B, T);
  k_proj<<<1184, GDIM>>>(emb, wih, V);

  const int nblk = (B + ROWS - 1) / ROWS;
  k_gru<<<nblk, NTHR>>>(tok, pos, whh, out, B, T);
}

// round 5
// speedup vs baseline: 1.8186x; 1.2181x over previous
#include <cuda_runtime.h>

typedef unsigned long long ull;
typedef long long ll;

#define HDIM 64
#define GDIM 192  // 3*HDIM
#define MAXT 256
#define MAXB 16384
#define MAXV 102400
#define NTHR 128  // 64 units x 2 row-halves
#define ROWS 4    // rows per CTA (2 per thread)

// ---------------- device globals (no allocation allowed) ----------------
__device__ int g_tok64;
__device__ int g_pos64;
__device__ int g_hist[256];
__device__ int g_order[MAXB];
__device__ float g_proj[(size_t)MAXV * GDIM];  // emb @ W_ih^T, ~78.6MB

// ---------------- helpers ----------------
__device__ __forceinline__ ull ffma2(ull a, ull b, ull c) {
  ull d;
  asm("fma.rn.f32x2 %0, %1, %2, %3;" : "=l"(d) : "l"(a), "l"(b), "l"(c));
  return d;
}
__device__ __forceinline__ float pair_sum(ull a) {
  unsigned lo, hi;
  asm("mov.b64 {%0, %1}, %2;" : "=r"(lo), "=r"(hi) : "l"(a));
  return __uint_as_float(lo) + __uint_as_float(hi);
}
__device__ __forceinline__ float rcp_fast(float x) {
  float y;
  asm("rcp.approx.f32 %0, %1;" : "=f"(y) : "f"(x));
  return y;
}
__device__ __forceinline__ float sigm(float x) {
  return rcp_fast(1.0f + __expf(-x));
}
__device__ __forceinline__ float tanh_f(float x) {
  return 1.0f - 2.0f * rcp_fast(__expf(2.0f * x) + 1.0f);
}
__device__ __forceinline__ int load_len_(const void* sp, int b, int T, int p64) {
  int v = p64 ? (int)((const ll*)sp)[b] : ((const int*)sp)[b];
  return min(max(v, 1), T);
}
__device__ __forceinline__ int load_tok_(const void* st, ll idx, int t64) {
  return t64 ? (int)((const ll*)st)[idx] : ((const int*)st)[idx];
}

// ---------------- preamble 1: dtype detect + length histogram (1 CTA) -------
__global__ void k_prep(const int* tok, const int* pos, int B, int T) {
  __shared__ int h_sm[256];
  int i = threadIdx.x;
  if (i == 0) {
    int t64 = 1, p64 = 1;
#pragma unroll
    for (int k = 1; k < 32; k += 2) {
      if (tok[k] != 0) t64 = 0;
      if (pos[k] != 0) p64 = 0;
    }
    g_tok64 = t64;
    g_pos64 = p64;
  }
  h_sm[i] = 0;
  __syncthreads();
  int p64 = g_pos64;
  for (int b = i; b < B; b += 256) {
    int v = p64 ? (int)((const ll*)pos)[b] : pos[b];
    int len = min(max(v, 1), T);
    atomicAdd(&h_sm[min(T - len, 255)], 1);  // bin 0 = longest
  }
  __syncthreads();
  g_hist[i] = h_sm[i];
}

// ---------------- preamble 2: scan + scatter (1 CTA) ----------------
__global__ void k_scanscatter(const void* pos, int B, int T) {
  __shared__ int v[256];
  __shared__ int cur[256];
  int i = threadIdx.x;
  int x = g_hist[i];
  v[i] = x;
  __syncthreads();
#pragma unroll
  for (int off = 1; off < 256; off <<= 1) {
    int t = (i >= off) ? v[i - off] : 0;
    __syncthreads();
    v[i] += t;
    __syncthreads();
  }
  cur[i] = v[i] - x;
  __syncthreads();
  int p64 = g_pos64;
  for (int b = i; b < B; b += 256) {
    int len = load_len_(pos, b, T, p64);
    int bin = min(T - len, 255);
    int p = atomicAdd(&cur[bin], 1);
    if (p < MAXB) g_order[p] = b;
  }
}

// ---------------- vocab projection: g_proj = emb @ W_ih^T ----------------
// thread j owns W_ih row j in registers; CTA processes a contiguous vocab
// chunk, EIGHT rows per iteration, double-buffered emb staging (128 loaders).
#define PROJ_RPI 8
__global__ void __launch_bounds__(GDIM, 3) k_proj(const float* __restrict__ emb,
                                                  const float* __restrict__ W_ih,
                                                  int V) {
  __shared__ __align__(16) float e_sm[2][PROJ_RPI][HDIM];
  const int j = threadIdx.x;

  ull w[32];
  {
    const ulonglong2* wr = (const ulonglong2*)(W_ih + j * HDIM);
#pragma unroll
    for (int k = 0; k < 16; k++) {
      ulonglong2 a = wr[k];
      w[2 * k] = a.x;
      w[2 * k + 1] = a.y;
    }
  }

  int per = (V + gridDim.x - 1) / gridDim.x;
  per = (per + PROJ_RPI - 1) & ~(PROJ_RPI - 1);
  const int vbeg = blockIdx.x * per;
  const int vend = min(vbeg + per, V);
  if (vbeg >= vend) return;

  // stage first 8 rows into buf 0 (128 loader threads, 1 float4 each)
  if (j < 128) {
    int row = j >> 4, lane = j & 15;
    int v = vbeg + row;
    if (v < vend)
      ((float4*)e_sm[0][row])[lane] = ((const float4*)(emb + (ll)v * HDIM))[lane];
  }
  __syncthreads();

  int buf = 0;
  for (int v = vbeg; v < vend; v += PROJ_RPI) {
    if (j < 128) {
      int row = j >> 4, lane = j & 15;
      int vn = v + PROJ_RPI + row;
      if (vn < vend)
        ((float4*)e_sm[buf ^ 1][row])[lane] =
            ((const float4*)(emb + (ll)vn * HDIM))[lane];
    }
    ull acc[PROJ_RPI];
#pragma unroll
    for (int i = 0; i < PROJ_RPI; i++) acc[i] = 0ull;
#pragma unroll
    for (int k = 0; k < 16; k++) {
#pragma unroll
      for (int i = 0; i < PROJ_RPI; i++) {
        ulonglong2 q = ((const ulonglong2*)e_sm[buf][i])[k];
        acc[i] = ffma2(w[2 * k], q.x, acc[i]);
        acc[i] = ffma2(w[2 * k + 1], q.y, acc[i]);
      }
    }
#pragma unroll
    for (int i = 0; i < PROJ_RPI; i++)
      if (v + i < vend) g_proj[(ll)(v + i) * GDIM + j] = pair_sum(acc[i]);
    __syncthreads();
    buf ^= 1;
  }
}

// ---------------- fused GRU recurrence ----------------
// CTA = 128 threads = (unit j in 0..63) x (rowhalf in 0..1); 4 rows per CTA.
// Each thread computes ALL THREE gates for its 2 rows entirely in-thread:
// W_hh rows {j, 64+j, 128+j} in registers (192 regs), h loaded from smem ONCE
// per k and reused for 3 gates. Double-buffered h -> ONE barrier per step.
__global__ void __launch_bounds__(NTHR, 2) k_gru(
    const void* __restrict__ seq_token, const void* __restrict__ seq_pos,
    const float* __restrict__ W_hh, float* __restrict__ out, int B, int T) {
  __shared__ int tok_sm[ROWS][MAXT];
  __shared__ __align__(16) float h_sm[2][ROWS][HDIM];
  __shared__ int s_row[ROWS], s_len[ROWS];

  const int tid = threadIdx.x;
  const int j = tid & 63;
  const int r0 = (tid >> 6) * 2;  // this thread's rows: r0, r0+1
  const int r1 = r0 + 1;
  const int tok64 = g_tok64;

  if (tid < ROWS) {
    int idx = ROWS * blockIdx.x + tid;
    int row = (idx < B) ? g_order[idx] : -1;
    s_row[tid] = row;
    s_len[tid] = (row >= 0) ? load_len_(seq_pos, row, T, g_pos64) : 0;
  }
  __syncthreads();
  int tmax = max(max(s_len[0], s_len[1]), max(s_len[2], s_len[3]));
  if (tmax > MAXT) tmax = MAXT;
  const int len0 = s_len[r0], len1 = s_len[r1];

  // stage token ids (as int32) into smem
#pragma unroll
  for (int r = 0; r < ROWS; r++) {
    int rw = s_row[r];
    for (int i = tid; i < tmax; i += NTHR)
      tok_sm[r][i] = (rw >= 0) ? load_tok_(seq_token, (ll)rw * T + i, tok64) : 0;
  }

  // W_hh rows for unit j, all 3 gates: 192 floats -> 96 ull regs
  ull wr[32], wz[32], wn[32];
  {
    const ulonglong2* p0 = (const ulonglong2*)(W_hh + j * HDIM);
    const ulonglong2* p1 = (const ulonglong2*)(W_hh + (HDIM + j) * HDIM);
    const ulonglong2* p2 = (const ulonglong2*)(W_hh + (2 * HDIM + j) * HDIM);
#pragma unroll
    for (int k = 0; k < 16; k++) {
      ulonglong2 a = p0[k];
      wr[2 * k] = a.x;
      wr[2 * k + 1] = a.y;
      ulonglong2 b = p1[k];
      wz[2 * k] = b.x;
      wz[2 * k + 1] = b.y;
      ulonglong2 c = p2[k];
      wn[2 * k] = c.x;
      wn[2 * k + 1] = c.y;
    }
  }

  // init h = 0 in buffer 0
  h_sm[0][r0][j] = 0.0f;
  h_sm[0][r1][j] = 0.0f;
  __syncthreads();  // tok_sm + h ready

  // gi for t=0 (3 gates x 2 rows)
  float gr0, gz0, gn0, gr1, gz1, gn1;
  {
    const float* p0 = g_proj + (ll)tok_sm[r0][0] * GDIM + j;
    const float* p1 = g_proj + (ll)tok_sm[r1][0] * GDIM + j;
    gr0 = p0[0]; gz0 = p0[64]; gn0 = p0[128];
    gr1 = p1[0]; gz1 = p1[64]; gn1 = p1[128];
  }

  for (int t = 0; t < tmax; t++) {
    const int cur = t & 1, nxt = cur ^ 1;

    // prefetch gi for t+1 (hidden under this step's dots)
    float pr0, pz0, pn0, pr1, pz1, pn1;
    if (t + 1 < tmax) {
      const float* p0 = g_proj + (ll)tok_sm[r0][t + 1] * GDIM + j;
      const float* p1 = g_proj + (ll)tok_sm[r1][t + 1] * GDIM + j;
      pr0 = p0[0]; pz0 = p0[64]; pn0 = p0[128];
      pr1 = p1[0]; pz1 = p1[64]; pn1 = p1[128];
    }

    // gh dots: 6 independent f32x2 chains, h loaded once per (row,k)
    ull ar0 = 0ull, az0 = 0ull, an0 = 0ull;
    ull ar1 = 0ull, az1 = 0ull, an1 = 0ull;
    const ulonglong2* hv0 = (const ulonglong2*)h_sm[cur][r0];
    const ulonglong2* hv1 = (const ulonglong2*)h_sm[cur][r1];
#pragma unroll
    for (int k = 0; k < 16; k++) {
      ulonglong2 h0 = hv0[k];
      ulonglong2 h1 = hv1[k];
      ar0 = ffma2(wr[2 * k], h0.x, ar0);
      ar0 = ffma2(wr[2 * k + 1], h0.y, ar0);
      az0 = ffma2(wz[2 * k], h0.x, az0);
      az0 = ffma2(wz[2 * k + 1], h0.y, az0);
      an0 = ffma2(wn[2 * k], h0.x, an0);
      an0 = ffma2(wn[2 * k + 1], h0.y, an0);
      ar1 = ffma2(wr[2 * k], h1.x, ar1);
      ar1 = ffma2(wr[2 * k + 1], h1.y, ar1);
      az1 = ffma2(wz[2 * k], h1.x, az1);
      az1 = ffma2(wz[2 * k + 1], h1.y, az1);
      an1 = ffma2(wn[2 * k], h1.x, an1);
      an1 = ffma2(wn[2 * k + 1], h1.y, an1);
    }

    // gates + h update, fully in-thread
    {
      float rr = sigm(gr0 + pair_sum(ar0));
      float zz = sigm(gz0 + pair_sum(az0));
      float nn = tanh_f(gn0 + rr * pair_sum(an0));
      float ho = h_sm[cur][r0][j];
      float hn = (1.0f - zz) * nn + zz * ho;
      h_sm[nxt][r0][j] = (t < len0) ? hn : ho;
    }
    {
      float rr = sigm(gr1 + pair_sum(ar1));
      float zz = sigm(gz1 + pair_sum(az1));
      float nn = tanh_f(gn1 + rr * pair_sum(an1));
      float ho = h_sm[cur][r1][j];
      float hn = (1.0f - zz) * nn + zz * ho;
      h_sm[nxt][r1][j] = (t < len1) ? hn : ho;
    }
    __syncthreads();  // h[nxt] complete; also fences reads of h[cur]

    gr0 = pr0; gz0 = pz0; gn0 = pn0;
    gr1 = pr1; gz1 = pz1; gn1 = pn1;
  }

  const int fb = tmax & 1;  // final h buffer
  {
    int row = s_row[r0];
    if (row >= 0) out[(ll)row * HDIM + j] = h_sm[fb][r0][j];
    row = s_row[r1];
    if (row >= 0) out[(ll)row * HDIM + j] = h_sm[fb][r1][j];
  }
}

// ---------------- launch ----------------
extern "C" void kernel_launch(void* const* d_in, const int* in_sizes, int n_in,
                              void* d_out, int out_size) {
  const void* tok = d_in[0];
  const void* pos = d_in[1];
  const float* emb = (const float*)d_in[2];
  const float* wih = (const float*)d_in[3];
  const float* whh = (const float*)d_in[4];
  float* out = (float*)d_out;

  const int B = in_sizes[1];
  const int T = in_sizes[0] / (B > 0 ? B : 1);
  int V = in_sizes[2] / HDIM;
  if (V > MAXV) V = MAXV;

  k_prep<<<1, 256>>>((const int*)tok, (const int*)pos, B, T);
  k_scanscatter<<<1, 256>>>(pos, B, T);
  k_proj<<<1184, GDIM>>>(emb, wih, V);

  const int nblk = (B + ROWS - 1) / ROWS;
  k_gru<<<nblk, NTHR>>>(tok, pos, whh, out, B, T);
}

// round 6
// speedup vs baseline: 2.2503x; 1.2374x over previous
#include <cuda_runtime.h>

typedef unsigned long long ull;
typedef long long ll;

#define HDIM 64
#define GDIM 192  // 3*HDIM
#define MAXT 256
#define MAXB 16384
#define MAXV 102400
#define NTHR 128  // (k-half) x (64 units) -> lane = kh*16 pattern
#define ROWS 4    // rows per CTA

// ---------------- device globals (no allocation allowed) ----------------
__device__ int g_tok64;
__device__ int g_pos64;
__device__ int g_hist[256];
__device__ int g_order[MAXB];
__device__ float g_proj[(size_t)MAXV * GDIM];  // emb @ W_ih^T, ~78.6MB

// ---------------- helpers ----------------
__device__ __forceinline__ ull ffma2(ull a, ull b, ull c) {
  ull d;
  asm("fma.rn.f32x2 %0, %1, %2, %3;" : "=l"(d) : "l"(a), "l"(b), "l"(c));
  return d;
}
__device__ __forceinline__ float pair_sum(ull a) {
  unsigned lo, hi;
  asm("mov.b64 {%0, %1}, %2;" : "=r"(lo), "=r"(hi) : "l"(a));
  return __uint_as_float(lo) + __uint_as_float(hi);
}
__device__ __forceinline__ float rcp_fast(float x) {
  float y;
  asm("rcp.approx.f32 %0, %1;" : "=f"(y) : "f"(x));
  return y;
}
__device__ __forceinline__ float sigm(float x) {
  return rcp_fast(1.0f + __expf(-x));
}
__device__ __forceinline__ float tanh_f(float x) {
  return 1.0f - 2.0f * rcp_fast(__expf(2.0f * x) + 1.0f);
}
__device__ __forceinline__ int load_len_(const void* sp, int b, int T, int p64) {
  int v = p64 ? (int)((const ll*)sp)[b] : ((const int*)sp)[b];
  return min(max(v, 1), T);
}
__device__ __forceinline__ int load_tok_(const void* st, ll idx, int t64) {
  return t64 ? (int)((const ll*)st)[idx] : ((const int*)st)[idx];
}

// ---------------- preamble 1: dtype detect + length histogram (1 CTA) -------
__global__ void k_prep(const int* tok, const int* pos, int B, int T) {
  __shared__ int h_sm[256];
  int i = threadIdx.x;
  if (i == 0) {
    int t64 = 1, p64 = 1;
#pragma unroll
    for (int k = 1; k < 32; k += 2) {
      if (tok[k] != 0) t64 = 0;
      if (pos[k] != 0) p64 = 0;
    }
    g_tok64 = t64;
    g_pos64 = p64;
  }
  h_sm[i] = 0;
  __syncthreads();
  int p64 = g_pos64;
  for (int b = i; b < B; b += 256) {
    int v = p64 ? (int)((const ll*)pos)[b] : pos[b];
    int len = min(max(v, 1), T);
    atomicAdd(&h_sm[min(T - len, 255)], 1);  // bin 0 = longest
  }
  __syncthreads();
  g_hist[i] = h_sm[i];
}

// ---------------- preamble 2: scan + scatter (1 CTA) ----------------
__global__ void k_scanscatter(const void* pos, int B, int T) {
  __shared__ int v[256];
  __shared__ int cur[256];
  int i = threadIdx.x;
  int x = g_hist[i];
  v[i] = x;
  __syncthreads();
#pragma unroll
  for (int off = 1; off < 256; off <<= 1) {
    int t = (i >= off) ? v[i - off] : 0;
    __syncthreads();
    v[i] += t;
    __syncthreads();
  }
  cur[i] = v[i] - x;
  __syncthreads();
  int p64 = g_pos64;
  for (int b = i; b < B; b += 256) {
    int len = load_len_(pos, b, T, p64);
    int bin = min(T - len, 255);
    int p = atomicAdd(&cur[bin], 1);
    if (p < MAXB) g_order[p] = b;
  }
}

// ---------------- vocab projection: g_proj = emb @ W_ih^T ----------------
#define PROJ_RPI 8
__global__ void __launch_bounds__(GDIM, 3) k_proj(const float* __restrict__ emb,
                                                  const float* __restrict__ W_ih,
                                                  int V) {
  __shared__ __align__(16) float e_sm[2][PROJ_RPI][HDIM];
  const int j = threadIdx.x;

  ull w[32];
  {
    const ulonglong2* wr = (const ulonglong2*)(W_ih + j * HDIM);
#pragma unroll
    for (int k = 0; k < 16; k++) {
      ulonglong2 a = wr[k];
      w[2 * k] = a.x;
      w[2 * k + 1] = a.y;
    }
  }

  int per = (V + gridDim.x - 1) / gridDim.x;
  per = (per + PROJ_RPI - 1) & ~(PROJ_RPI - 1);
  const int vbeg = blockIdx.x * per;
  const int vend = min(vbeg + per, V);
  if (vbeg >= vend) return;

  if (j < 128) {
    int row = j >> 4, lane = j & 15;
    int v = vbeg + row;
    if (v < vend)
      ((float4*)e_sm[0][row])[lane] = ((const float4*)(emb + (ll)v * HDIM))[lane];
  }
  __syncthreads();

  int buf = 0;
  for (int v = vbeg; v < vend; v += PROJ_RPI) {
    if (j < 128) {
      int row = j >> 4, lane = j & 15;
      int vn = v + PROJ_RPI + row;
      if (vn < vend)
        ((float4*)e_sm[buf ^ 1][row])[lane] =
            ((const float4*)(emb + (ll)vn * HDIM))[lane];
    }
    ull acc[PROJ_RPI];
#pragma unroll
    for (int i = 0; i < PROJ_RPI; i++) acc[i] = 0ull;
#pragma unroll
    for (int k = 0; k < 16; k++) {
#pragma unroll
      for (int i = 0; i < PROJ_RPI; i++) {
        ulonglong2 q = ((const ulonglong2*)e_sm[buf][i])[k];
        acc[i] = ffma2(w[2 * k], q.x, acc[i]);
        acc[i] = ffma2(w[2 * k + 1], q.y, acc[i]);
      }
    }
#pragma unroll
    for (int i = 0; i < PROJ_RPI; i++)
      if (v + i < vend) g_proj[(ll)(v + i) * GDIM + j] = pair_sum(acc[i]);
    __syncthreads();
    buf ^= 1;
  }
}

// ---------------- fused GRU recurrence (k-split) ----------------
// CTA = 128 threads. lane mapping: kh = (tid>>4)&1 (k-half), j = (tid&15) +
// 16*(tid>>5) (unit 0..63). Thread computes PARTIAL dots (its 32 k's) for all
// 4 rows x 3 gates (12 chains, W-half in 96 regs), combines with partner
// (lane^16, same warp) via shfl.xor, then finishes gates + h-update for its
// own 2 rows (kh=0 -> rows 0,1; kh=1 -> rows 2,3). One barrier per step.
// h stored per k-half with 36-float stride (bank-disjoint broadcast lines).
__global__ void __launch_bounds__(NTHR, 3) k_gru(
    const void* __restrict__ seq_token, const void* __restrict__ seq_pos,
    const float* __restrict__ W_hh, float* __restrict__ out, int B, int T) {
  __shared__ int tok_sm[ROWS][MAXT];
  __shared__ __align__(16) float h_sm[2][ROWS][2][36];  // [buf][row][khalf][32+pad]
  __shared__ int s_row[ROWS], s_len[ROWS];

  const int tid = threadIdx.x;
  const int kh = (tid >> 4) & 1;
  const int j = (tid & 15) | ((tid >> 5) << 4);
  const int rA = kh * 2, rB = rA + 1;  // own rows
  const int tok64 = g_tok64;

  if (tid < ROWS) {
    int idx = ROWS * blockIdx.x + tid;
    int row = (idx < B) ? g_order[idx] : -1;
    s_row[tid] = row;
    s_len[tid] = (row >= 0) ? load_len_(seq_pos, row, T, g_pos64) : 0;
  }
  __syncthreads();
  int tmax = max(max(s_len[0], s_len[1]), max(s_len[2], s_len[3]));
  if (tmax > MAXT) tmax = MAXT;
  const int lenA = s_len[rA], lenB = s_len[rB];

  // stage token ids (as int32) into smem
#pragma unroll
  for (int r = 0; r < ROWS; r++) {
    int rw = s_row[r];
    for (int i = tid; i < tmax; i += NTHR)
      tok_sm[r][i] = (rw >= 0) ? load_tok_(seq_token, (ll)rw * T + i, tok64) : 0;
  }

  // W_hh half-rows for unit j, 3 gates: 96 floats -> 48 ull regs
  ull wr[16], wz[16], wn[16];
  {
    const ulonglong2* p0 = (const ulonglong2*)(W_hh + j * HDIM + kh * 32);
    const ulonglong2* p1 = (const ulonglong2*)(W_hh + (HDIM + j) * HDIM + kh * 32);
    const ulonglong2* p2 = (const ulonglong2*)(W_hh + (2 * HDIM + j) * HDIM + kh * 32);
#pragma unroll
    for (int k = 0; k < 8; k++) {
      ulonglong2 a = p0[k];
      wr[2 * k] = a.x;
      wr[2 * k + 1] = a.y;
      ulonglong2 b = p1[k];
      wz[2 * k] = b.x;
      wz[2 * k + 1] = b.y;
      ulonglong2 c = p2[k];
      wn[2 * k] = c.x;
      wn[2 * k + 1] = c.y;
    }
  }

  // init h = 0 in buffer 0 (each thread inits its own-row slots)
  h_sm[0][rA][j >> 5][j & 31] = 0.0f;
  h_sm[0][rB][j >> 5][j & 31] = 0.0f;
  __syncthreads();  // tok_sm + h ready

  // gi for t=0 (own 2 rows x 3 gates)
  float grA, gzA, gnA, grB, gzB, gnB;
  {
    const float* pA = g_proj + (ll)tok_sm[rA][0] * GDIM + j;
    const float* pB = g_proj + (ll)tok_sm[rB][0] * GDIM + j;
    grA = pA[0]; gzA = pA[64]; gnA = pA[128];
    grB = pB[0]; gzB = pB[64]; gnB = pB[128];
  }

  for (int t = 0; t < tmax; t++) {
    const int cur = t & 1, nxt = cur ^ 1;

    // prefetch gi for t+1
    float qrA = 0.f, qzA = 0.f, qnA = 0.f, qrB = 0.f, qzB = 0.f, qnB = 0.f;
    if (t + 1 < tmax) {
      const float* pA = g_proj + (ll)tok_sm[rA][t + 1] * GDIM + j;
      const float* pB = g_proj + (ll)tok_sm[rB][t + 1] * GDIM + j;
      qrA = pA[0]; qzA = pA[64]; qnA = pA[128];
      qrB = pB[0]; qzB = pB[64]; qnB = pB[128];
    }

    // partial dots over this thread's k-half, all 4 rows x 3 gates
    ull acc[ROWS][3];
#pragma unroll
    for (int r = 0; r < ROWS; r++) {
      acc[r][0] = 0ull;
      acc[r][1] = 0ull;
      acc[r][2] = 0ull;
    }
#pragma unroll
    for (int k = 0; k < 8; k++) {
#pragma unroll
      for (int r = 0; r < ROWS; r++) {
        ulonglong2 hq = ((const ulonglong2*)h_sm[cur][r][kh])[k];
        acc[r][0] = ffma2(wr[2 * k], hq.x, acc[r][0]);
        acc[r][0] = ffma2(wr[2 * k + 1], hq.y, acc[r][0]);
        acc[r][1] = ffma2(wz[2 * k], hq.x, acc[r][1]);
        acc[r][1] = ffma2(wz[2 * k + 1], hq.y, acc[r][1]);
        acc[r][2] = ffma2(wn[2 * k], hq.x, acc[r][2]);
        acc[r][2] = ffma2(wn[2 * k + 1], hq.y, acc[r][2]);
      }
    }

    // combine halves with partner lane (lane ^ 16); all lanes execute all
    // 12 shfls; results consumed via kh-selects so none get DCE'd.
    float f[ROWS][3];
#pragma unroll
    for (int r = 0; r < ROWS; r++) {
#pragma unroll
      for (int gg = 0; gg < 3; gg++) {
        float p = pair_sum(acc[r][gg]);
        f[r][gg] = p + __shfl_xor_sync(0xffffffffu, p, 16);
      }
    }
    const float phrA = f[rA][0], phzA = f[rA][1], phnA = f[rA][2];
    const float phrB = f[rB][0], phzB = f[rB][1], phnB = f[rB][2];

    // gates + h update for own rows, fully in-thread
    {
      float rr = sigm(grA + phrA);
      float zz = sigm(gzA + phzA);
      float nn = tanh_f(gnA + rr * phnA);
      float ho = h_sm[cur][rA][j >> 5][j & 31];
      float hn = (1.0f - zz) * nn + zz * ho;
      h_sm[nxt][rA][j >> 5][j & 31] = (t < lenA) ? hn : ho;
    }
    {
      float rr = sigm(grB + phrB);
      float zz = sigm(gzB + phzB);
      float nn = tanh_f(gnB + rr * phnB);
      float ho = h_sm[cur][rB][j >> 5][j & 31];
      float hn = (1.0f - zz) * nn + zz * ho;
      h_sm[nxt][rB][j >> 5][j & 31] = (t < lenB) ? hn : ho;
    }
    __syncthreads();  // h[nxt] complete; fences reads of h[cur]

    grA = qrA; gzA = qzA; gnA = qnA;
    grB = qrB; gzB = qzB; gnB = qnB;
  }

  const int fb = tmax & 1;  // final h buffer
  {
    int row = s_row[rA];
    if (row >= 0) out[(ll)row * HDIM + j] = h_sm[fb][rA][j >> 5][j & 31];
    row = s_row[rB];
    if (row >= 0) out[(ll)row * HDIM + j] = h_sm[fb][rB][j >> 5][j & 31];
  }
}

// ---------------- launch ----------------
extern "C" void kernel_launch(void* const* d_in, const int* in_sizes, int n_in,
                              void* d_out, int out_size) {
  const void* tok = d_in[0];
  const void* pos = d_in[1];
  const float* emb = (const float*)d_in[2];
  const float* wih = (const float*)d_in[3];
  const float* whh = (const float*)d_in[4];
  float* out = (float*)d_out;

  const int B = in_sizes[1];
  const int T = in_sizes[0] / (B > 0 ? B : 1);
  int V = in_sizes[2] / HDIM;
  if (V > MAXV) V = MAXV;

  k_prep<<<1, 256>>>((const int*)tok, (const int*)pos, B, T);
  k_scanscatter<<<1, 256>>>(pos, B, T);
  k_proj<<<1184, GDIM>>>(emb, wih, V);

  const int nblk = (B + ROWS - 1) / ROWS;
  k_gru<<<nblk, NTHR>>>(tok, pos, whh, out, B, T);
}